// round 1
// baseline (speedup 1.0000x reference)
#include <cuda_runtime.h>
#include <cuda_bf16.h>
#include <math.h>

// ---------------- problem constants ----------------
constexpr int B = 4, S = 1024, D = 512, M = 64, H = 8, WIN = 128;
constexpr int T = M + S;            // 1088
constexpr int BT = B * T;           // 4352
constexpr int HD = D / H;           // 64
constexpr float LR = 1e-3f, WD = 1e-2f, MAX_ALR = 0.1f, EPS = 1e-8f;
constexpr size_t BTD = (size_t)BT * D;

// ---------------- scratch (static device globals; no allocation) ----------------
__device__ float g_xm[BTD];
__device__ float g_q[BTD];
__device__ float g_k[BTD];
__device__ float g_v[BTD];
__device__ float g_w[BT];
__device__ float g_z1[BTD];
__device__ float g_h1[BTD];
__device__ float g_z2[BTD];
__device__ float g_preds[BTD];
__device__ float g_g2[BTD];
__device__ float g_dz2[BTD];
__device__ float g_dh1[BTD];
__device__ float g_dz1[BTD];
__device__ float g_gW[2 * D * D];
__device__ float g_gb[2 * D];
__device__ float g_Wu[2 * D * D];
__device__ float g_bu[2 * D];
__device__ float g_r1[BTD];
__device__ float g_r[BTD];
__device__ float g_qs[BTD];
__device__ float g_ks[BTD];
__device__ float g_vs[BTD];
__device__ float g_o[BTD];

// ---------------- GEMM: C[M,N] = op(A,B) with epilogue ----------------
// MODE: 0 = NN (A[M,K], B[K,N]); 1 = NT (A[M,K], B[N,K]); 2 = TN (A[K,M], B[K,N])
// EPI : 0 = C = AB + bias; 1 = C = AB; 2 = Z = AB + bias, C = R + silu(Z) (Z stored if Zout)
#define GEMM_NN 0
#define GEMM_NT 1
#define GEMM_TN 2
#define EPI_BIAS 0
#define EPI_NONE 1
#define EPI_RESSILU 2

template <int MODE, int EPI>
__global__ void gemm_kernel(const float* __restrict__ A, const float* __restrict__ Bm,
                            const float* __restrict__ bias, const float* __restrict__ R,
                            float* __restrict__ C, float* __restrict__ Zout,
                            int Md, int Nd, int Kd) {
    constexpr int BM = 64, BN = 64, BK = 16;
    __shared__ float As[BK][BM + 1];
    __shared__ float Bs[BK][BN + 1];
    const int n0 = blockIdx.x * BN;
    const int m0 = blockIdx.y * BM;
    const int tx = threadIdx.x % 16;
    const int ty = threadIdx.x / 16;
    float acc[4][4] = {};
    for (int k0 = 0; k0 < Kd; k0 += BK) {
        // load A tile -> As[k][m]
        for (int i = threadIdx.x; i < BM * BK; i += 256) {
            if (MODE == GEMM_TN) {
                int mm = i % BM, kk = i / BM;
                As[kk][mm] = A[(size_t)(k0 + kk) * Md + (m0 + mm)];
            } else {
                int kk = i % BK, mm = i / BK;
                As[kk][mm] = A[(size_t)(m0 + mm) * Kd + (k0 + kk)];
            }
        }
        // load B tile -> Bs[k][n]
        for (int i = threadIdx.x; i < BN * BK; i += 256) {
            if (MODE == GEMM_NT) {
                int kk = i % BK, nn = i / BK;
                Bs[kk][nn] = Bm[(size_t)(n0 + nn) * Kd + (k0 + kk)];
            } else {
                int nn = i % BN, kk = i / BN;
                Bs[kk][nn] = Bm[(size_t)(k0 + kk) * Nd + (n0 + nn)];
            }
        }
        __syncthreads();
#pragma unroll
        for (int kk = 0; kk < BK; kk++) {
            float a[4], bv[4];
#pragma unroll
            for (int i = 0; i < 4; i++) a[i] = As[kk][ty * 4 + i];
#pragma unroll
            for (int j = 0; j < 4; j++) bv[j] = Bs[kk][tx * 4 + j];
#pragma unroll
            for (int i = 0; i < 4; i++)
#pragma unroll
                for (int j = 0; j < 4; j++) acc[i][j] += a[i] * bv[j];
        }
        __syncthreads();
    }
#pragma unroll
    for (int i = 0; i < 4; i++) {
        int m = m0 + ty * 4 + i;
#pragma unroll
        for (int j = 0; j < 4; j++) {
            int n = n0 + tx * 4 + j;
            float val = acc[i][j];
            if (EPI == EPI_BIAS || EPI == EPI_RESSILU) val += bias[n];
            size_t off = (size_t)m * Nd + n;
            if (EPI == EPI_RESSILU) {
                if (Zout) Zout[off] = val;
                float sig = 1.f / (1.f + __expf(-val));
                val = R[off] + val * sig;
            }
            C[off] = val;
        }
    }
}

// ---------------- elementwise / small kernels ----------------
__global__ void build_xm_kernel(const float* __restrict__ x, const float* __restrict__ meta,
                                float* __restrict__ xm) {
    size_t idx = (size_t)blockIdx.x * blockDim.x + threadIdx.x;
    if (idx >= BTD) return;
    int d = idx % D;
    int t = (idx / D) % T;
    int b = idx / ((size_t)D * T);
    xm[idx] = (t < M) ? meta[(size_t)t * D + d] : x[((size_t)b * S + (t - M)) * D + d];
}

__global__ void wlr_kernel(const float* __restrict__ xm, const float* __restrict__ Wlr,
                           const float* __restrict__ blr, float* __restrict__ w) {
    __shared__ float sm[256];
    int row = blockIdx.x;
    const float* xr = xm + (size_t)row * D;
    float s = 0.f;
    for (int d = threadIdx.x; d < D; d += 256) s += xr[d] * Wlr[d];
    sm[threadIdx.x] = s;
    __syncthreads();
    for (int st = 128; st > 0; st >>= 1) {
        if (threadIdx.x < st) sm[threadIdx.x] += sm[threadIdx.x + st];
        __syncthreads();
    }
    if (threadIdx.x == 0) {
        float z = sm[0] + blr[0];
        w[row] = (1.f / (1.f + __expf(-z))) * MAX_ALR;
    }
}

__device__ __forceinline__ float silu_grad(float z) {
    float sig = 1.f / (1.f + __expf(-z));
    return sig * (1.f + z * (1.f - sig));
}

__global__ void grad_out_kernel(const float* __restrict__ preds, const float* __restrict__ v,
                                const float* __restrict__ w, const float* __restrict__ z2,
                                float* __restrict__ g2, float* __restrict__ dz2) {
    size_t i = (size_t)blockIdx.x * blockDim.x + threadIdx.x;
    if (i >= BTD) return;
    int row = i / D;
    float g = w[row] * (2.0f / (float)D) * (preds[i] - v[i]);
    g2[i] = g;
    dz2[i] = g * silu_grad(z2[i]);
}

__global__ void dz1_kernel(const float* __restrict__ g2, const float* __restrict__ dh1,
                           const float* __restrict__ z1, float* __restrict__ dz1) {
    size_t i = (size_t)blockIdx.x * blockDim.x + threadIdx.x;
    if (i >= BTD) return;
    dz1[i] = (g2[i] + dh1[i]) * silu_grad(z1[i]);
}

__global__ void colsum_kernel(const float* __restrict__ X, float* __restrict__ out, int rows) {
    int c = threadIdx.x;  // blockDim = 512 = D
    int r0 = blockIdx.x * 64;
    int r1 = min(r0 + 64, rows);
    float s = 0.f;
    for (int r = r0; r < r1; r++) s += X[(size_t)r * D + c];
    atomicAdd(&out[c], s);
}

__global__ void adamw_kernel(const float* __restrict__ p, const float* __restrict__ g,
                             float* __restrict__ out, int n) {
    int i = blockIdx.x * blockDim.x + threadIdx.x;
    if (i >= n) return;
    float gv = g[i];
    out[i] = p[i] * (1.f - LR * WD) - LR * gv / (fabsf(gv) + EPS);
}

// ---------------- sliding window attention ----------------
// one block per (i - M, h, b); 128 threads
__global__ void attn_kernel(const float* __restrict__ qs, const float* __restrict__ ks,
                            const float* __restrict__ vs, float* __restrict__ o) {
    const int i = blockIdx.x + M;
    const int h = blockIdx.y;
    const int b = blockIdx.z;
    const int j0 = max(0, i - (WIN - 1));
    const int nj = i - j0 + 1;
    __shared__ float Ks[WIN][HD + 1];
    __shared__ float qsh[HD];
    __shared__ float sc[WIN];
    __shared__ float red[128];
    const int tid = threadIdx.x;
    const float* qp = qs + ((size_t)(b * T + i)) * D + h * HD;
    if (tid < HD) qsh[tid] = qp[tid];
    for (int idx = tid; idx < nj * HD; idx += 128) {
        int j = idx >> 6, d = idx & 63;
        Ks[j][d] = ks[((size_t)(b * T + j0 + j)) * D + h * HD + d];
    }
    __syncthreads();
    float s = -1e30f;
    if (tid < nj) {
        float acc = 0.f;
#pragma unroll
        for (int d = 0; d < HD; d++) acc += qsh[d] * Ks[tid][d];
        s = acc * 0.125f;  // 1/sqrt(64)
        sc[tid] = s;
    }
    red[tid] = s;
    __syncthreads();
    for (int st = 64; st > 0; st >>= 1) {
        if (tid < st) red[tid] = fmaxf(red[tid], red[tid + st]);
        __syncthreads();
    }
    float mx = red[0];
    __syncthreads();
    float p = 0.f;
    if (tid < nj) {
        p = __expf(sc[tid] - mx);
        sc[tid] = p;
    }
    red[tid] = p;
    __syncthreads();
    for (int st = 64; st > 0; st >>= 1) {
        if (tid < st) red[tid] += red[tid + st];
        __syncthreads();
    }
    float inv = 1.f / red[0];
    __syncthreads();
    if (tid < HD) {
        float acc = 0.f;
        const float* vp = vs + ((size_t)(b * T + j0)) * D + h * HD + tid;
        for (int j = 0; j < nj; j++) acc += sc[j] * vp[(size_t)j * D];
        o[((size_t)(b * T + i)) * D + h * HD + tid] = acc * inv;
    }
}

// ---------------- host-side launch ----------------
template <int MODE, int EPI>
static void launch_gemm(const float* A, const float* Bm, const float* bias, const float* R,
                        float* C, float* Z, int Md, int Nd, int Kd) {
    dim3 grid(Nd / 64, Md / 64);
    gemm_kernel<MODE, EPI><<<grid, 256>>>(A, Bm, bias, R, C, Z, Md, Nd, Kd);
}

template <typename Tsym>
static float* sym(Tsym& s) {
    void* p = nullptr;
    cudaGetSymbolAddress(&p, s);
    return (float*)p;
}

extern "C" void kernel_launch(void* const* d_in, const int* in_sizes, int n_in,
                              void* d_out, int out_size) {
    const float* x     = (const float*)d_in[0];
    const float* meta  = (const float*)d_in[1];
    const float* lmm_W = (const float*)d_in[2];
    const float* lmm_b = (const float*)d_in[3];
    const float* Wq    = (const float*)d_in[4];
    const float* bq    = (const float*)d_in[5];
    const float* Wk    = (const float*)d_in[6];
    const float* bk    = (const float*)d_in[7];
    const float* Wv    = (const float*)d_in[8];
    const float* bv    = (const float*)d_in[9];
    const float* W_lr  = (const float*)d_in[10];
    const float* b_lr  = (const float*)d_in[11];
    const float* swa_W = (const float*)d_in[12];
    const float* swa_b = (const float*)d_in[13];
    float* out = (float*)d_out;

    float *xm = sym(g_xm), *q = sym(g_q), *k = sym(g_k), *v = sym(g_v), *w = sym(g_w);
    float *z1 = sym(g_z1), *h1 = sym(g_h1), *z2 = sym(g_z2), *preds = sym(g_preds);
    float *g2 = sym(g_g2), *dz2 = sym(g_dz2), *dh1 = sym(g_dh1), *dz1 = sym(g_dz1);
    float *gW = sym(g_gW), *gb = sym(g_gb), *Wu = sym(g_Wu), *bu = sym(g_bu);
    float *r1 = sym(g_r1), *r = sym(g_r), *qs = sym(g_qs), *ks = sym(g_ks), *vs = sym(g_vs);
    float *o = sym(g_o);

    const int EW_BLK = 256;
    const int ew_grid = (int)((BTD + EW_BLK - 1) / EW_BLK);

    // 1) xm = [meta ; x]
    build_xm_kernel<<<ew_grid, EW_BLK>>>(x, meta, xm);

    // 2) projections
    launch_gemm<GEMM_NN, EPI_BIAS>(xm, Wq, bq, nullptr, q, nullptr, BT, D, D);
    launch_gemm<GEMM_NN, EPI_BIAS>(xm, Wk, bk, nullptr, k, nullptr, BT, D, D);
    launch_gemm<GEMM_NN, EPI_BIAS>(xm, Wv, bv, nullptr, v, nullptr, BT, D, D);

    // 3) adaptive lr
    wlr_kernel<<<BT, 256>>>(xm, W_lr, b_lr, w);

    // 4) lmm forward on k (save z1, z2, h1, preds)
    launch_gemm<GEMM_NN, EPI_RESSILU>(k, lmm_W, lmm_b, k, h1, z1, BT, D, D);
    launch_gemm<GEMM_NN, EPI_RESSILU>(h1, lmm_W + D * D, lmm_b + D, h1, preds, z2, BT, D, D);

    // 5) backward
    grad_out_kernel<<<ew_grid, EW_BLK>>>(preds, v, w, z2, g2, dz2);
    cudaMemsetAsync(gb, 0, 2 * D * sizeof(float));
    launch_gemm<GEMM_TN, EPI_NONE>(h1, dz2, nullptr, nullptr, gW + D * D, nullptr, D, D, BT);
    colsum_kernel<<<(BT + 63) / 64, D>>>(dz2, gb + D, BT);
    launch_gemm<GEMM_NT, EPI_NONE>(dz2, lmm_W + D * D, nullptr, nullptr, dh1, nullptr, BT, D, D);
    dz1_kernel<<<ew_grid, EW_BLK>>>(g2, dh1, z1, dz1);
    launch_gemm<GEMM_TN, EPI_NONE>(k, dz1, nullptr, nullptr, gW, nullptr, D, D, BT);
    colsum_kernel<<<(BT + 63) / 64, D>>>(dz1, gb, BT);

    // 6) AdamW-style update
    adamw_kernel<<<(2 * D * D + 255) / 256, 256>>>(lmm_W, gW, Wu, 2 * D * D);
    adamw_kernel<<<(2 * D + 255) / 256, 256>>>(lmm_b, gb, bu, 2 * D);

    // 7) retrieval with updated memory
    launch_gemm<GEMM_NN, EPI_RESSILU>(q, Wu, bu, q, r1, nullptr, BT, D, D);
    launch_gemm<GEMM_NN, EPI_RESSILU>(r1, Wu + D * D, bu + D, r1, r, nullptr, BT, D, D);

    // 8) SWA projections
    launch_gemm<GEMM_NN, EPI_BIAS>(r, swa_W + 0 * D * D, swa_b + 0 * D, nullptr, qs, nullptr, BT, D, D);
    launch_gemm<GEMM_NN, EPI_BIAS>(r, swa_W + 1 * D * D, swa_b + 1 * D, nullptr, ks, nullptr, BT, D, D);
    launch_gemm<GEMM_NN, EPI_BIAS>(r, swa_W + 2 * D * D, swa_b + 2 * D, nullptr, vs, nullptr, BT, D, D);

    // 9) attention (only rows i >= M are needed downstream)
    {
        dim3 grid(S, H, B);
        attn_kernel<<<grid, 128>>>(qs, ks, vs, o);
    }

    // 10) output projection per batch, writing sliced rows directly into d_out
    for (int b = 0; b < B; b++) {
        const float* Ab = o + ((size_t)(b * T + M)) * D;
        float* Cb = out + (size_t)b * S * D;
        launch_gemm<GEMM_NN, EPI_BIAS>(Ab, swa_W + 3 * D * D, swa_b + 3 * D, nullptr, Cb, nullptr, S, D, D);
    }
}

// round 2
// speedup vs baseline: 4.9035x; 4.9035x over previous
#include <cuda_runtime.h>
#include <cuda_bf16.h>
#include <math.h>
#include <stdint.h>

// ---------------- problem constants ----------------
constexpr int B = 4, S = 1024, D = 512, M = 64, H = 8, WIN = 128;
constexpr int T = M + S;            // 1088
constexpr int BT = B * T;           // 4352
constexpr int HD = D / H;           // 64
constexpr float LR = 1e-3f, WD = 1e-2f, MAX_ALR = 0.1f, EPS = 1e-8f;
constexpr size_t BTD = (size_t)BT * D;
constexpr int SPLK = 8;             // split-K factor for TN grad GEMMs (4352/8=544=17*32)

// ---------------- scratch (static device globals; no allocation) ----------------
__device__ float g_xm[BTD];
__device__ float g_q[BTD];
__device__ float g_k[BTD];
__device__ float g_v[BTD];
__device__ float g_w[BT];
__device__ float g_z1[BTD];
__device__ float g_h1[BTD];
__device__ float g_z2[BTD];
__device__ float g_preds[BTD];
__device__ float g_g2[BTD];
__device__ float g_dz2[BTD];
__device__ float g_dh1[BTD];
__device__ float g_dz1[BTD];
__device__ float g_gW[2 * D * D];
__device__ float g_gb[2 * D];
__device__ float g_Wu[2 * D * D];
__device__ float g_bu[2 * D];
__device__ float g_r1[BTD];
__device__ float g_r[BTD];
__device__ float g_qs[BTD];
__device__ float g_ks[BTD];
__device__ float g_vs[BTD];
__device__ float g_o[BTD];
__device__ float g_part[SPLK * D * D];

// ---------------- tf32 helpers ----------------
__device__ __forceinline__ uint32_t f2tf32(float x) {
    uint32_t r;
    asm("cvt.rna.tf32.f32 %0, %1;" : "=r"(r) : "f"(x));
    return r;
}

__device__ __forceinline__ void mma_tf32(float* d, const uint32_t* a, const uint32_t* b) {
    asm volatile(
        "mma.sync.aligned.m16n8k8.row.col.f32.tf32.tf32.f32 "
        "{%0,%1,%2,%3}, {%4,%5,%6,%7}, {%8,%9}, {%0,%1,%2,%3};"
        : "+f"(d[0]), "+f"(d[1]), "+f"(d[2]), "+f"(d[3])
        : "r"(a[0]), "r"(a[1]), "r"(a[2]), "r"(a[3]), "r"(b[0]), "r"(b[1]));
}

// swizzled [p][32] layout (128B rows, float4-group XOR swizzle)
__device__ __forceinline__ uint32_t lds_swz(const uint32_t* Sm, int p, int k) {
    return Sm[p * 32 + ((((k >> 2) ^ (p & 7)) << 2) | (k & 3))];
}

// ---------------- tf32 MMA GEMM ----------------
// MODE: 0 = NN (A[M,K], B[K,N]); 1 = NT (A[M,K], B[N,K]); 2 = TN (A[K,M], B[K,N])
// EPI : 0 = C = AB + bias; 1 = C = AB; 2 = Z = AB + bias, C = R + silu(Z) (Z stored if Zout)
#define GEMM_NN 0
#define GEMM_NT 1
#define GEMM_TN 2
#define EPI_BIAS 0
#define EPI_NONE 1
#define EPI_RESSILU 2

constexpr int BMt = 128, BNt = 128, BKt = 32;

template <int MODE, int EPI, int SPLITK>
__global__ __launch_bounds__(256) void mma_gemm(
    const float* __restrict__ A, const float* __restrict__ Bm,
    const float* __restrict__ bias, const float* __restrict__ R,
    float* __restrict__ C, float* __restrict__ Zout,
    int Md, int Nd, int Kd) {
    __shared__ uint32_t As[32 * 136];  // pad layout max (4352 u32); swz uses 4096
    __shared__ uint32_t Bs[32 * 136];

    const int m0 = blockIdx.y * BMt;
    const int n0 = blockIdx.x * BNt;
    const int tid = threadIdx.x;
    const int warp = tid >> 5, lane = tid & 31;
    const int wm = warp >> 2, wn = warp & 3;    // 2 x 4 warp grid
    const int gid = lane >> 2, tig = lane & 3;

    int kbeg = 0, kend = Kd;
    if (SPLITK > 1) {
        int chunk = Kd / SPLITK;
        kbeg = blockIdx.z * chunk;
        kend = kbeg + chunk;
    }

    float acc[4][4][4];
#pragma unroll
    for (int i = 0; i < 4; i++)
#pragma unroll
        for (int j = 0; j < 4; j++)
#pragma unroll
            for (int c = 0; c < 4; c++) acc[i][j][c] = 0.f;

    for (int k0 = kbeg; k0 < kend; k0 += BKt) {
        // ---- load A tile ----
        if (MODE == GEMM_TN) {
            // A [Kd, Md]; pad layout As[k*136 + m]
            int mg = tid & 31, kr = tid >> 5;
#pragma unroll
            for (int r = 0; r < 4; r++) {
                int k = kr + r * 8;
                float4 vA = *(const float4*)(A + (size_t)(k0 + k) * Md + m0 + mg * 4);
                uint32_t* dst = &As[k * 136 + mg * 4];
                dst[0] = f2tf32(vA.x); dst[1] = f2tf32(vA.y);
                dst[2] = f2tf32(vA.z); dst[3] = f2tf32(vA.w);
            }
        } else {
            // A [Md, Kd]; swz layout As[m][k]
            int kg = tid & 7, mr = tid >> 3;
#pragma unroll
            for (int r = 0; r < 4; r++) {
                int m = mr + r * 32;
                float4 vA = *(const float4*)(A + (size_t)(m0 + m) * Kd + k0 + kg * 4);
                int g = kg ^ (m & 7);
                uint32_t* dst = &As[m * 32 + g * 4];
                dst[0] = f2tf32(vA.x); dst[1] = f2tf32(vA.y);
                dst[2] = f2tf32(vA.z); dst[3] = f2tf32(vA.w);
            }
        }
        // ---- load B tile ----
        if (MODE == GEMM_NT) {
            // B [Nd, Kd]; swz layout Bs[n][k]
            int kg = tid & 7, nr = tid >> 3;
#pragma unroll
            for (int r = 0; r < 4; r++) {
                int n = nr + r * 32;
                float4 vB = *(const float4*)(Bm + (size_t)(n0 + n) * Kd + k0 + kg * 4);
                int g = kg ^ (n & 7);
                uint32_t* dst = &Bs[n * 32 + g * 4];
                dst[0] = f2tf32(vB.x); dst[1] = f2tf32(vB.y);
                dst[2] = f2tf32(vB.z); dst[3] = f2tf32(vB.w);
            }
        } else {
            // B [Kd, Nd]; pad layout Bs[k*136 + n]
            int ng = tid & 31, kr = tid >> 5;
#pragma unroll
            for (int r = 0; r < 4; r++) {
                int k = kr + r * 8;
                float4 vB = *(const float4*)(Bm + (size_t)(k0 + k) * Nd + n0 + ng * 4);
                uint32_t* dst = &Bs[k * 136 + ng * 4];
                dst[0] = f2tf32(vB.x); dst[1] = f2tf32(vB.y);
                dst[2] = f2tf32(vB.z); dst[3] = f2tf32(vB.w);
            }
        }
        __syncthreads();

#pragma unroll
        for (int kk = 0; kk < BKt; kk += 8) {
            uint32_t afr[4][4], bfr[4][2];
#pragma unroll
            for (int im = 0; im < 4; im++) {
                int mrow = wm * 64 + im * 16 + gid;
                if (MODE == GEMM_TN) {
                    afr[im][0] = As[(kk + tig) * 136 + mrow];
                    afr[im][1] = As[(kk + tig) * 136 + mrow + 8];
                    afr[im][2] = As[(kk + tig + 4) * 136 + mrow];
                    afr[im][3] = As[(kk + tig + 4) * 136 + mrow + 8];
                } else {
                    afr[im][0] = lds_swz(As, mrow, kk + tig);
                    afr[im][1] = lds_swz(As, mrow + 8, kk + tig);
                    afr[im][2] = lds_swz(As, mrow, kk + tig + 4);
                    afr[im][3] = lds_swz(As, mrow + 8, kk + tig + 4);
                }
            }
#pragma unroll
            for (int jn = 0; jn < 4; jn++) {
                int ncol = wn * 32 + jn * 8 + gid;
                if (MODE == GEMM_NT) {
                    bfr[jn][0] = lds_swz(Bs, ncol, kk + tig);
                    bfr[jn][1] = lds_swz(Bs, ncol, kk + tig + 4);
                } else {
                    bfr[jn][0] = Bs[(kk + tig) * 136 + ncol];
                    bfr[jn][1] = Bs[(kk + tig + 4) * 136 + ncol];
                }
            }
#pragma unroll
            for (int im = 0; im < 4; im++)
#pragma unroll
                for (int jn = 0; jn < 4; jn++)
                    mma_tf32(acc[im][jn], afr[im], bfr[jn]);
        }
        __syncthreads();
    }

    // ---- epilogue ----
    size_t Cbase = 0;
    if (SPLITK > 1) Cbase = (size_t)blockIdx.z * Md * Nd;
#pragma unroll
    for (int im = 0; im < 4; im++) {
#pragma unroll
        for (int jn = 0; jn < 4; jn++) {
            int row = m0 + wm * 64 + im * 16 + gid;
            int col = n0 + wn * 32 + jn * 8 + tig * 2;
#pragma unroll
            for (int rr = 0; rr < 2; rr++) {
                int r_ = row + rr * 8;
                float v0 = acc[im][jn][rr * 2 + 0];
                float v1 = acc[im][jn][rr * 2 + 1];
                if (EPI == EPI_BIAS || EPI == EPI_RESSILU) {
                    v0 += bias[col];
                    v1 += bias[col + 1];
                }
                size_t off = (size_t)r_ * Nd + col;
                if (EPI == EPI_RESSILU) {
                    if (Zout) { Zout[off] = v0; Zout[off + 1] = v1; }
                    float s0 = 1.f / (1.f + __expf(-v0));
                    float s1 = 1.f / (1.f + __expf(-v1));
                    v0 = R[off] + v0 * s0;
                    v1 = R[off + 1] + v1 * s1;
                }
                C[Cbase + off] = v0;
                C[Cbase + off + 1] = v1;
            }
        }
    }
}

// ---------------- split-K reduce ----------------
__global__ void reduce_part_kernel(const float* __restrict__ part, float* __restrict__ out, int n) {
    int i = blockIdx.x * 256 + threadIdx.x;
    if (i >= n) return;
    float s = 0.f;
#pragma unroll
    for (int z = 0; z < SPLK; z++) s += part[(size_t)z * n + i];
    out[i] = s;
}

// ---------------- elementwise / small kernels ----------------
__global__ void build_xm_kernel(const float* __restrict__ x, const float* __restrict__ meta,
                                float* __restrict__ xm) {
    size_t idx = (size_t)blockIdx.x * blockDim.x + threadIdx.x;
    if (idx >= BTD) return;
    int d = idx % D;
    int t = (idx / D) % T;
    int b = idx / ((size_t)D * T);
    xm[idx] = (t < M) ? meta[(size_t)t * D + d] : x[((size_t)b * S + (t - M)) * D + d];
}

__global__ void wlr_kernel(const float* __restrict__ xm, const float* __restrict__ Wlr,
                           const float* __restrict__ blr, float* __restrict__ w) {
    __shared__ float sm[256];
    int row = blockIdx.x;
    const float* xr = xm + (size_t)row * D;
    float s = 0.f;
    for (int d = threadIdx.x; d < D; d += 256) s += xr[d] * Wlr[d];
    sm[threadIdx.x] = s;
    __syncthreads();
    for (int st = 128; st > 0; st >>= 1) {
        if (threadIdx.x < st) sm[threadIdx.x] += sm[threadIdx.x + st];
        __syncthreads();
    }
    if (threadIdx.x == 0) {
        float z = sm[0] + blr[0];
        w[row] = (1.f / (1.f + __expf(-z))) * MAX_ALR;
    }
}

__device__ __forceinline__ float silu_grad(float z) {
    float sig = 1.f / (1.f + __expf(-z));
    return sig * (1.f + z * (1.f - sig));
}

__global__ void grad_out_kernel(const float* __restrict__ preds, const float* __restrict__ v,
                                const float* __restrict__ w, const float* __restrict__ z2,
                                float* __restrict__ g2, float* __restrict__ dz2) {
    size_t i = (size_t)blockIdx.x * blockDim.x + threadIdx.x;
    if (i >= BTD) return;
    int row = i / D;
    float g = w[row] * (2.0f / (float)D) * (preds[i] - v[i]);
    g2[i] = g;
    dz2[i] = g * silu_grad(z2[i]);
}

__global__ void dz1_kernel(const float* __restrict__ g2, const float* __restrict__ dh1,
                           const float* __restrict__ z1, float* __restrict__ dz1) {
    size_t i = (size_t)blockIdx.x * blockDim.x + threadIdx.x;
    if (i >= BTD) return;
    dz1[i] = (g2[i] + dh1[i]) * silu_grad(z1[i]);
}

__global__ void colsum_kernel(const float* __restrict__ X, float* __restrict__ out, int rows) {
    int c = threadIdx.x;  // blockDim = 512 = D
    int r0 = blockIdx.x * 64;
    int r1 = min(r0 + 64, rows);
    float s = 0.f;
    for (int r = r0; r < r1; r++) s += X[(size_t)r * D + c];
    atomicAdd(&out[c], s);
}

__global__ void adamw_kernel(const float* __restrict__ p, const float* __restrict__ g,
                             float* __restrict__ out, int n) {
    int i = blockIdx.x * blockDim.x + threadIdx.x;
    if (i >= n) return;
    float gv = g[i];
    out[i] = p[i] * (1.f - LR * WD) - LR * gv / (fabsf(gv) + EPS);
}

// ---------------- sliding window attention (8 queries / block) ----------------
constexpr int QB = 8;
constexpr int KROWS = WIN + QB - 1;  // 135

__global__ __launch_bounds__(128) void attn_kernel2(
    const float* __restrict__ qs, const float* __restrict__ ks,
    const float* __restrict__ vs, float* __restrict__ o) {
    __shared__ float Ksm[KROWS * 65];
    __shared__ float Qsm[QB * 64];
    __shared__ float sc[QB * 128];
    __shared__ float invs[QB];

    const int i0 = M + blockIdx.x * QB;  // first query token index (>= M)
    const int h = blockIdx.y;
    const int b = blockIdx.z;
    const int tid = threadIdx.x;
    const int lane = tid & 31, w = tid >> 5;

    const int jlo = max(0, i0 - (WIN - 1));
    const int jhi = i0 + QB - 1;
    const int nrows = jhi - jlo + 1;  // <= 135

    // load K rows [jlo, jhi] into smem (stride 65)
    for (int idx = tid; idx < nrows * 64; idx += 128) {
        int r = idx >> 6, d = idx & 63;
        Ksm[r * 65 + d] = ks[((size_t)(b * T + jlo + r)) * D + h * HD + d];
    }
    // load Q rows
    for (int idx = tid; idx < QB * 64; idx += 128) {
        int q = idx >> 6, d = idx & 63;
        Qsm[idx] = qs[((size_t)(b * T + i0 + q)) * D + h * HD + d];
    }
    __syncthreads();

    // scores: thread tid covers window slot jj = tid for each query q
#pragma unroll
    for (int q = 0; q < QB; q++) {
        int iq = i0 + q;
        int j = iq - (WIN - 1) + tid;
        float s = -1e30f;
        if (j >= 0) {
            int r = j - jlo;
            const float* kp = &Ksm[r * 65];
            const float* qp = &Qsm[q * 64];
            float acc = 0.f;
#pragma unroll
            for (int d = 0; d < HD; d++) acc += qp[d] * kp[d];
            s = acc * 0.125f;  // 1/sqrt(64)
        }
        sc[q * 128 + tid] = s;
    }
    __syncthreads();

    // softmax per query: warp w handles q = w and q = w+4 (no block syncs needed)
    for (int q = w; q < QB; q += 4) {
        float x0 = sc[q * 128 + lane];
        float x1 = sc[q * 128 + lane + 32];
        float x2 = sc[q * 128 + lane + 64];
        float x3 = sc[q * 128 + lane + 96];
        float mx = fmaxf(fmaxf(x0, x1), fmaxf(x2, x3));
#pragma unroll
        for (int off = 16; off > 0; off >>= 1) mx = fmaxf(mx, __shfl_xor_sync(0xffffffffu, mx, off));
        float e0 = __expf(x0 - mx), e1 = __expf(x1 - mx), e2 = __expf(x2 - mx), e3 = __expf(x3 - mx);
        sc[q * 128 + lane] = e0;
        sc[q * 128 + lane + 32] = e1;
        sc[q * 128 + lane + 64] = e2;
        sc[q * 128 + lane + 96] = e3;
        float sum = e0 + e1 + e2 + e3;
#pragma unroll
        for (int off = 16; off > 0; off >>= 1) sum += __shfl_xor_sync(0xffffffffu, sum, off);
        if (lane == 0) invs[q] = 1.f / sum;
    }
    __syncthreads();

    // V accumulation: thread handles d = tid&63, queries g, g+2, g+4, g+6
    const int d = tid & 63, g = tid >> 6;
    float acc[4] = {0.f, 0.f, 0.f, 0.f};
    for (int r = 0; r < nrows; r++) {
        float vv = vs[((size_t)(b * T + jlo + r)) * D + h * HD + d];
        int j = jlo + r;
#pragma unroll
        for (int qi = 0; qi < 4; qi++) {
            int q = g + qi * 2;
            int jj = j - (i0 + q) + (WIN - 1);
            if (jj >= 0 && jj < WIN) acc[qi] += sc[q * 128 + jj] * vv;
        }
    }
#pragma unroll
    for (int qi = 0; qi < 4; qi++) {
        int q = g + qi * 2;
        o[((size_t)(b * T + i0 + q)) * D + h * HD + d] = acc[qi] * invs[q];
    }
}

// ---------------- host-side launch ----------------
template <int MODE, int EPI>
static void launch_gemm(const float* A, const float* Bm, const float* bias, const float* R,
                        float* C, float* Z, int Md, int Nd, int Kd) {
    dim3 grid(Nd / BNt, Md / BMt);
    mma_gemm<MODE, EPI, 1><<<grid, 256>>>(A, Bm, bias, R, C, Z, Md, Nd, Kd);
}

static void launch_gemm_tn_splitk(const float* A, const float* Bm, float* part,
                                  int Md, int Nd, int Kd) {
    dim3 grid(Nd / BNt, Md / BMt, SPLK);
    mma_gemm<GEMM_TN, EPI_NONE, SPLK><<<grid, 256>>>(A, Bm, nullptr, nullptr, part, nullptr, Md, Nd, Kd);
}

template <typename Tsym>
static float* sym(Tsym& s) {
    void* p = nullptr;
    cudaGetSymbolAddress(&p, s);
    return (float*)p;
}

extern "C" void kernel_launch(void* const* d_in, const int* in_sizes, int n_in,
                              void* d_out, int out_size) {
    const float* x     = (const float*)d_in[0];
    const float* meta  = (const float*)d_in[1];
    const float* lmm_W = (const float*)d_in[2];
    const float* lmm_b = (const float*)d_in[3];
    const float* Wq    = (const float*)d_in[4];
    const float* bq    = (const float*)d_in[5];
    const float* Wk    = (const float*)d_in[6];
    const float* bk    = (const float*)d_in[7];
    const float* Wv    = (const float*)d_in[8];
    const float* bv    = (const float*)d_in[9];
    const float* W_lr  = (const float*)d_in[10];
    const float* b_lr  = (const float*)d_in[11];
    const float* swa_W = (const float*)d_in[12];
    const float* swa_b = (const float*)d_in[13];
    float* out = (float*)d_out;

    float *xm = sym(g_xm), *q = sym(g_q), *k = sym(g_k), *v = sym(g_v), *w = sym(g_w);
    float *z1 = sym(g_z1), *h1 = sym(g_h1), *z2 = sym(g_z2), *preds = sym(g_preds);
    float *g2 = sym(g_g2), *dz2 = sym(g_dz2), *dh1 = sym(g_dh1), *dz1 = sym(g_dz1);
    float *gW = sym(g_gW), *gb = sym(g_gb), *Wu = sym(g_Wu), *bu = sym(g_bu);
    float *r1 = sym(g_r1), *r = sym(g_r), *qs = sym(g_qs), *ks = sym(g_ks), *vs = sym(g_vs);
    float *o = sym(g_o), *part = sym(g_part);

    const int EW_BLK = 256;
    const int ew_grid = (int)((BTD + EW_BLK - 1) / EW_BLK);

    // 1) xm = [meta ; x]
    build_xm_kernel<<<ew_grid, EW_BLK>>>(x, meta, xm);

    // 2) projections
    launch_gemm<GEMM_NN, EPI_BIAS>(xm, Wq, bq, nullptr, q, nullptr, BT, D, D);
    launch_gemm<GEMM_NN, EPI_BIAS>(xm, Wk, bk, nullptr, k, nullptr, BT, D, D);
    launch_gemm<GEMM_NN, EPI_BIAS>(xm, Wv, bv, nullptr, v, nullptr, BT, D, D);

    // 3) adaptive lr
    wlr_kernel<<<BT, 256>>>(xm, W_lr, b_lr, w);

    // 4) lmm forward on k (save z1, z2, h1, preds)
    launch_gemm<GEMM_NN, EPI_RESSILU>(k, lmm_W, lmm_b, k, h1, z1, BT, D, D);
    launch_gemm<GEMM_NN, EPI_RESSILU>(h1, lmm_W + D * D, lmm_b + D, h1, preds, z2, BT, D, D);

    // 5) backward
    grad_out_kernel<<<ew_grid, EW_BLK>>>(preds, v, w, z2, g2, dz2);
    cudaMemsetAsync(gb, 0, 2 * D * sizeof(float));
    launch_gemm_tn_splitk(h1, dz2, part, D, D, BT);
    reduce_part_kernel<<<(D * D + 255) / 256, 256>>>(part, gW + D * D, D * D);
    colsum_kernel<<<(BT + 63) / 64, D>>>(dz2, gb + D, BT);
    launch_gemm<GEMM_NT, EPI_NONE>(dz2, lmm_W + D * D, nullptr, nullptr, dh1, nullptr, BT, D, D);
    dz1_kernel<<<ew_grid, EW_BLK>>>(g2, dh1, z1, dz1);
    launch_gemm_tn_splitk(k, dz1, part, D, D, BT);
    reduce_part_kernel<<<(D * D + 255) / 256, 256>>>(part, gW, D * D);
    colsum_kernel<<<(BT + 63) / 64, D>>>(dz1, gb, BT);

    // 6) AdamW-style update
    adamw_kernel<<<(2 * D * D + 255) / 256, 256>>>(lmm_W, gW, Wu, 2 * D * D);
    adamw_kernel<<<(2 * D + 255) / 256, 256>>>(lmm_b, gb, bu, 2 * D);

    // 7) retrieval with updated memory
    launch_gemm<GEMM_NN, EPI_RESSILU>(q, Wu, bu, q, r1, nullptr, BT, D, D);
    launch_gemm<GEMM_NN, EPI_RESSILU>(r1, Wu + D * D, bu + D, r1, r, nullptr, BT, D, D);

    // 8) SWA projections
    launch_gemm<GEMM_NN, EPI_BIAS>(r, swa_W + 0 * D * D, swa_b + 0 * D, nullptr, qs, nullptr, BT, D, D);
    launch_gemm<GEMM_NN, EPI_BIAS>(r, swa_W + 1 * D * D, swa_b + 1 * D, nullptr, ks, nullptr, BT, D, D);
    launch_gemm<GEMM_NN, EPI_BIAS>(r, swa_W + 2 * D * D, swa_b + 2 * D, nullptr, vs, nullptr, BT, D, D);

    // 9) attention (only rows i >= M are needed downstream)
    {
        dim3 grid(S / QB, H, B);
        attn_kernel2<<<grid, 128>>>(qs, ks, vs, o);
    }

    // 10) output projection per batch, writing sliced rows directly into d_out
    for (int b = 0; b < B; b++) {
        const float* Ab = o + ((size_t)(b * T + M)) * D;
        float* Cb = out + (size_t)b * S * D;
        launch_gemm<GEMM_NN, EPI_BIAS>(Ab, swa_W + 3 * D * D, swa_b + 3 * D, nullptr, Cb, nullptr, S, D, D);
    }
}